// round 1
// baseline (speedup 1.0000x reference)
#include <cuda_runtime.h>

// LTC MemoryCell: B=32, T=128, d=128, units=256, ODE_UNFOLDS=6.
// Sparsity: each target unit j couples only to {j, j +/- d} recurrently and to
// sensory source (j mod d). => (v[b,j], v[b,j+d]) is an independent 2-dim
// recurrence per (b, j<d). One thread per (b,j) pair; all params in registers.

#define Dn      128
#define UNITS   256
#define Tn      128
#define UNFOLDS 6
#define EPSc    1e-8f
#define LOG2E   1.4426950408889634f

__device__ __forceinline__ float ex2f(float x) {
    float y; asm("ex2.approx.ftz.f32 %0, %1;" : "=f"(y) : "f"(x)); return y;
}
__device__ __forceinline__ float rcpf(float x) {
    float y; asm("rcp.approx.ftz.f32 %0, %1;" : "=f"(y) : "f"(x)); return y;
}

__global__ void __launch_bounds__(Dn, 1) ltc_kernel(
    const float* __restrict__ X,       // (B,T,d)
    const float* __restrict__ in_w,    // (d)
    const float* __restrict__ in_b,    // (d)
    const float* __restrict__ out_w,   // (d)
    const float* __restrict__ out_b,   // (d)
    const float* __restrict__ gleak,   // (units)
    const float* __restrict__ vleak,   // (units)
    const float* __restrict__ cm,      // (units)
    const float* __restrict__ w,       // (units,units)
    const float* __restrict__ mu,      // (units,units)
    const float* __restrict__ sigma,   // (units,units)
    const float* __restrict__ erev,    // (units,units)
    const float* __restrict__ sw,      // (d,units)
    const float* __restrict__ smu,     // (d,units)
    const float* __restrict__ ssig,    // (d,units)
    const float* __restrict__ serev,   // (d,units)
    float* __restrict__ out)           // (B,d)
{
    const int j  = threadIdx.x;        // pair index, 0..d-1
    const int b  = blockIdx.x;         // batch index
    const int jc = j + Dn;             // partner unit

    // --- synapse flat indices (row-major (src, tgt)) ---
    const int i_aa = j  * UNITS + j;   // src j   -> tgt j
    const int i_ca = jc * UNITS + j;   // src j+d -> tgt j
    const int i_cc = jc * UNITS + jc;  // src j+d -> tgt j+d
    const int i_ac = j  * UNITS + jc;  // src j   -> tgt j+d

    // sigmoid((v-mu)*sig) = 1/(1+exp2((mu-v)*sig*log2e))
    // precompute c1 = -sig*log2e, c0 = mu*sig*log2e  -> arg = fma(c1, v, c0)
    float sg, m;
    sg = __ldg(sigma + i_aa); m = __ldg(mu + i_aa);
    const float c1_aa = -sg * LOG2E, c0_aa = m * sg * LOG2E;
    sg = __ldg(sigma + i_ca); m = __ldg(mu + i_ca);
    const float c1_ca = -sg * LOG2E, c0_ca = m * sg * LOG2E;
    sg = __ldg(sigma + i_cc); m = __ldg(mu + i_cc);
    const float c1_cc = -sg * LOG2E, c0_cc = m * sg * LOG2E;
    sg = __ldg(sigma + i_ac); m = __ldg(mu + i_ac);
    const float c1_ac = -sg * LOG2E, c0_ac = m * sg * LOG2E;

    const float w_aa = __ldg(w + i_aa), we_aa = w_aa * __ldg(erev + i_aa);
    const float w_ca = __ldg(w + i_ca), we_ca = w_ca * __ldg(erev + i_ca);
    const float w_cc = __ldg(w + i_cc), we_cc = w_cc * __ldg(erev + i_cc);
    const float w_ac = __ldg(w + i_ac), we_ac = w_ac * __ldg(erev + i_ac);

    // sensory synapses: src j -> tgt j (A) and src j -> tgt j+d (C)
    const int is_a = j * UNITS + j;
    const int is_c = j * UNITS + jc;
    sg = __ldg(ssig + is_a); m = __ldg(smu + is_a);
    const float sc1A = -sg * LOG2E, sc0A = m * sg * LOG2E;
    sg = __ldg(ssig + is_c); m = __ldg(smu + is_c);
    const float sc1C = -sg * LOG2E, sc0C = m * sg * LOG2E;
    const float swA = __ldg(sw + is_a), serA = __ldg(serev + is_a);
    const float swC = __ldg(sw + is_c), serC = __ldg(serev + is_c);

    // per-unit params
    const float glA = __ldg(gleak + j),  glC = __ldg(gleak + jc);
    const float vlA = __ldg(vleak + j),  vlC = __ldg(vleak + jc);
    const float cmtA = __ldg(cm + j)  * (float)UNFOLDS;
    const float cmtC = __ldg(cm + jc) * (float)UNFOLDS;
    const float glvlA = glA * vlA,  glvlC = glC * vlC;
    const float cgA = cmtA + glA,   cgC = cmtC + glC;

    const float inw = __ldg(in_w + j), inb = __ldg(in_b + j);
    const float ow  = __ldg(out_w + j), ob = __ldg(out_b + j);

    const float* xp = X + ((size_t)b * Tn) * Dn + j;

    float vA = 0.0f, vC = 0.0f;
    float xnext = __ldg(xp);                 // prefetch t=0

    #pragma unroll 1
    for (int t = 0; t < Tn; ++t) {
        const float xraw = xnext;
        if (t + 1 < Tn) xnext = __ldg(xp + (t + 1) * Dn);   // hide L2 latency
        const float xt = fmaf(xraw, inw, inb);

        // sensory activations (once per timestep)
        const float saA = swA * rcpf(1.0f + ex2f(fmaf(sc1A, xt, sc0A)));
        const float saC = swC * rcpf(1.0f + ex2f(fmaf(sc1C, xt, sc0C)));
        const float nbA = fmaf(saA, serA, glvlA);   // gleak*vleak + wnum_s
        const float dbA = cgA + saA;                // cm_t + gleak + wden_s
        const float nbC = fmaf(saC, serC, glvlC);
        const float dbC = cgC + saC;

        #pragma unroll
        for (int u = 0; u < UNFOLDS; ++u) {
            const float sAA = rcpf(1.0f + ex2f(fmaf(c1_aa, vA, c0_aa)));
            const float sCA = rcpf(1.0f + ex2f(fmaf(c1_ca, vC, c0_ca)));
            const float sCC = rcpf(1.0f + ex2f(fmaf(c1_cc, vC, c0_cc)));
            const float sAC = rcpf(1.0f + ex2f(fmaf(c1_ac, vA, c0_ac)));

            float numA = fmaf(cmtA, vA, nbA);
            numA = fmaf(we_aa, sAA, numA);
            numA = fmaf(we_ca, sCA, numA);
            float denA = fmaf(w_aa, sAA, dbA);
            denA = fmaf(w_ca, sCA, denA);

            float numC = fmaf(cmtC, vC, nbC);
            numC = fmaf(we_cc, sCC, numC);
            numC = fmaf(we_ac, sAC, numC);
            float denC = fmaf(w_cc, sCC, dbC);
            denC = fmaf(w_ac, sAC, denC);

            vA = numA * rcpf(denA + EPSc);
            vC = numC * rcpf(denC + EPSc);
        }
    }

    out[b * Dn + j] = fmaf(vA, ow, ob);
}

extern "C" void kernel_launch(void* const* d_in, const int* in_sizes, int n_in,
                              void* d_out, int out_size) {
    const float* X     = (const float*)d_in[0];
    const float* in_w  = (const float*)d_in[1];
    const float* in_b  = (const float*)d_in[2];
    const float* out_w = (const float*)d_in[3];
    const float* out_b = (const float*)d_in[4];
    const float* gleak = (const float*)d_in[5];
    const float* vleak = (const float*)d_in[6];
    const float* cmp   = (const float*)d_in[7];
    const float* w     = (const float*)d_in[8];
    const float* mu    = (const float*)d_in[9];
    const float* sigma = (const float*)d_in[10];
    const float* erev  = (const float*)d_in[11];
    const float* sw    = (const float*)d_in[12];
    const float* smu   = (const float*)d_in[13];
    const float* ssig  = (const float*)d_in[14];
    const float* serev = (const float*)d_in[15];
    float* out = (float*)d_out;

    const int B = in_sizes[0] / (Tn * Dn);   // 32
    ltc_kernel<<<B, Dn>>>(X, in_w, in_b, out_w, out_b,
                          gleak, vleak, cmp, w, mu, sigma, erev,
                          sw, smu, ssig, serev, out);
}

// round 2
// speedup vs baseline: 1.4041x; 1.4041x over previous
#include <cuda_runtime.h>

// LTC MemoryCell: B=32, T=128, d=128, units=256, ODE_UNFOLDS=6.
// Each (v[b,j], v[b,j+d]) pair is an independent 2-dim recurrence.
// One thread per (b,j); all params in registers.
//
// R2: sigmoid via MUFU tanh (sigmoid(z)=0.5+0.5*tanh(z/2), constants folded),
//     and carry (num, D) instead of v so every v-consumer is an FFMA against
//     rcp(D) with its multiplier precomputed in the rcp shadow.

#define Dn      128
#define UNITS   256
#define Tn      128
#define UNFOLDS 6
#define EPSc    1e-8f

__device__ __forceinline__ float tanhf_(float x) {
    float y; asm("tanh.approx.f32 %0, %1;" : "=f"(y) : "f"(x)); return y;
}
__device__ __forceinline__ float rcpf(float x) {
    float y; asm("rcp.approx.ftz.f32 %0, %1;" : "=f"(y) : "f"(x)); return y;
}

__global__ void __launch_bounds__(Dn, 1) ltc_kernel(
    const float* __restrict__ X,       // (B,T,d)
    const float* __restrict__ in_w,    // (d)
    const float* __restrict__ in_b,    // (d)
    const float* __restrict__ out_w,   // (d)
    const float* __restrict__ out_b,   // (d)
    const float* __restrict__ gleak,   // (units)
    const float* __restrict__ vleak,   // (units)
    const float* __restrict__ cm,      // (units)
    const float* __restrict__ w,       // (units,units)
    const float* __restrict__ mu,      // (units,units)
    const float* __restrict__ sigma,   // (units,units)
    const float* __restrict__ erev,    // (units,units)
    const float* __restrict__ sw,      // (d,units)
    const float* __restrict__ smu,     // (d,units)
    const float* __restrict__ ssig,    // (d,units)
    const float* __restrict__ serev,   // (d,units)
    float* __restrict__ out)           // (B,d)
{
    const int j  = threadIdx.x;        // pair index, 0..d-1
    const int b  = blockIdx.x;         // batch index
    const int jc = j + Dn;             // partner unit

    // synapse flat indices (row-major (src, tgt))
    const int i_aa = j  * UNITS + j;   // j   -> j
    const int i_ca = jc * UNITS + j;   // j+d -> j
    const int i_cc = jc * UNITS + jc;  // j+d -> j+d
    const int i_ac = j  * UNITS + jc;  // j   -> j+d

    // sigmoid((v-mu)*sig) = 0.5 + 0.5*tanh(0.5*sig*v - 0.5*sig*mu)
    float sg, m;
    sg = __ldg(sigma + i_aa); m = __ldg(mu + i_aa);
    const float c1_aa = 0.5f * sg, c0_aa = -0.5f * sg * m;
    sg = __ldg(sigma + i_ca); m = __ldg(mu + i_ca);
    const float c1_ca = 0.5f * sg, c0_ca = -0.5f * sg * m;
    sg = __ldg(sigma + i_cc); m = __ldg(mu + i_cc);
    const float c1_cc = 0.5f * sg, c0_cc = -0.5f * sg * m;
    sg = __ldg(sigma + i_ac); m = __ldg(mu + i_ac);
    const float c1_ac = 0.5f * sg, c0_ac = -0.5f * sg * m;

    // w*sigmoid = 0.5*w + (0.5*w)*tanh ; same for w*erev
    const float w2_aa = 0.5f * __ldg(w + i_aa), we2_aa = w2_aa * __ldg(erev + i_aa);
    const float w2_ca = 0.5f * __ldg(w + i_ca), we2_ca = w2_ca * __ldg(erev + i_ca);
    const float w2_cc = 0.5f * __ldg(w + i_cc), we2_cc = w2_cc * __ldg(erev + i_cc);
    const float w2_ac = 0.5f * __ldg(w + i_ac), we2_ac = w2_ac * __ldg(erev + i_ac);

    // sensory synapses: src j -> tgt j (A) and src j -> tgt j+d (C)
    const int is_a = j * UNITS + j;
    const int is_c = j * UNITS + jc;
    sg = __ldg(ssig + is_a); m = __ldg(smu + is_a);
    const float sc1A = 0.5f * sg, sc0A = -0.5f * sg * m;
    sg = __ldg(ssig + is_c); m = __ldg(smu + is_c);
    const float sc1C = 0.5f * sg, sc0C = -0.5f * sg * m;
    const float sw2A = 0.5f * __ldg(sw + is_a), ser2A = sw2A * __ldg(serev + is_a);
    const float sw2C = 0.5f * __ldg(sw + is_c), ser2C = sw2C * __ldg(serev + is_c);

    // per-unit params
    const float glA = __ldg(gleak + j),  glC = __ldg(gleak + jc);
    const float vlA = __ldg(vleak + j),  vlC = __ldg(vleak + jc);
    const float cmtA = __ldg(cm + j)  * (float)UNFOLDS;
    const float cmtC = __ldg(cm + jc) * (float)UNFOLDS;

    // static parts of num/den bases (tanh half-weights folded in; EPS in den)
    const float numBaseA = fmaf(glA, vlA, we2_aa + we2_ca);
    const float numBaseC = fmaf(glC, vlC, we2_cc + we2_ac);
    const float denBaseA = cmtA + glA + w2_aa + w2_ca + EPSc;
    const float denBaseC = cmtC + glC + w2_cc + w2_ac + EPSc;

    const float inw = __ldg(in_w + j), inb = __ldg(in_b + j);
    const float ow  = __ldg(out_w + j), ob = __ldg(out_b + j);

    const float* xp = X + ((size_t)b * Tn) * Dn + j;

    // carry (num, D) with v = num * rcp(D); v0 = 0
    float numA = 0.0f, DA = 1.0f;
    float numC = 0.0f, DC = 1.0f;
    float xnext = __ldg(xp);                 // prefetch t=0

    #pragma unroll 1
    for (int t = 0; t < Tn; ++t) {
        const float xraw = xnext;
        if (t + 1 < Tn) xnext = __ldg(xp + (t + 1) * Dn);   // hide L2 latency
        const float xt = fmaf(xraw, inw, inb);

        // sensory activations (once per timestep): sa = sw2 + sw2*tanh
        const float thsA = tanhf_(fmaf(sc1A, xt, sc0A));
        const float thsC = tanhf_(fmaf(sc1C, xt, sc0C));
        // nb = numBase + sa*serev ; db = denBase + sa
        const float nbA = fmaf(ser2A, thsA, numBaseA + ser2A);
        const float dbA = fmaf(sw2A,  thsA, denBaseA + sw2A);
        const float nbC = fmaf(ser2C, thsC, numBaseC + ser2C);
        const float dbC = fmaf(sw2C,  thsC, denBaseC + sw2C);

        #pragma unroll
        for (int u = 0; u < UNFOLDS; ++u) {
            const float rdA = rcpf(DA);
            const float rdC = rcpf(DC);
            // multipliers computed in the rcp shadow (depend only on num)
            const float pAA = c1_aa * numA;
            const float pAC = c1_ac * numA;
            const float pmA = cmtA * numA;
            const float pCA = c1_ca * numC;
            const float pCC = c1_cc * numC;
            const float pmC = cmtC * numC;

            const float thAA = tanhf_(fmaf(pAA, rdA, c0_aa));
            const float thAC = tanhf_(fmaf(pAC, rdA, c0_ac));
            const float thCA = tanhf_(fmaf(pCA, rdC, c0_ca));
            const float thCC = tanhf_(fmaf(pCC, rdC, c0_cc));

            float nA = fmaf(pmA, rdA, nbA);
            nA = fmaf(we2_aa, thAA, nA);
            nA = fmaf(we2_ca, thCA, nA);
            float dA = fmaf(w2_aa, thAA, dbA);
            dA = fmaf(w2_ca, thCA, dA);

            float nC = fmaf(pmC, rdC, nbC);
            nC = fmaf(we2_cc, thCC, nC);
            nC = fmaf(we2_ac, thAC, nC);
            float dC = fmaf(w2_cc, thCC, dbC);
            dC = fmaf(w2_ac, thAC, dC);

            numA = nA; DA = dA;
            numC = nC; DC = dC;
        }
    }

    const float vA = numA * rcpf(DA);
    out[b * Dn + j] = fmaf(vA, ow, ob);
}

extern "C" void kernel_launch(void* const* d_in, const int* in_sizes, int n_in,
                              void* d_out, int out_size) {
    const float* X     = (const float*)d_in[0];
    const float* in_w  = (const float*)d_in[1];
    const float* in_b  = (const float*)d_in[2];
    const float* out_w = (const float*)d_in[3];
    const float* out_b = (const float*)d_in[4];
    const float* gleak = (const float*)d_in[5];
    const float* vleak = (const float*)d_in[6];
    const float* cmp   = (const float*)d_in[7];
    const float* w     = (const float*)d_in[8];
    const float* mu    = (const float*)d_in[9];
    const float* sigma = (const float*)d_in[10];
    const float* erev  = (const float*)d_in[11];
    const float* sw    = (const float*)d_in[12];
    const float* smu   = (const float*)d_in[13];
    const float* ssig  = (const float*)d_in[14];
    const float* serev = (const float*)d_in[15];
    float* out = (float*)d_out;

    const int B = in_sizes[0] / (Tn * Dn);   // 32
    ltc_kernel<<<B, Dn>>>(X, in_w, in_b, out_w, out_b,
                          gleak, vleak, cmp, w, mu, sigma, erev,
                          sw, smu, ssig, serev, out);
}

// round 3
// speedup vs baseline: 1.4787x; 1.0531x over previous
#include <cuda_runtime.h>

// LTC MemoryCell: B=32, T=128, d=128, units=256, ODE_UNFOLDS=6.
// Each (v[b,j], v[b,j+d]) pair is an independent 2-dim recurrence.
// One thread per (b,j); all params in registers.
//
// R3: software-pipeline the sensory (x-dependent) computation one timestep
//     ahead so the per-timestep serial prologue (x FFMA -> 2 tanh -> db/nb)
//     hides inside the previous timestep's unfold chain; branchless prefetch;
//     outer unroll 2.

#define Dn      128
#define UNITS   256
#define Tn      128
#define UNFOLDS 6
#define EPSc    1e-8f

__device__ __forceinline__ float tanhf_(float x) {
    float y; asm("tanh.approx.f32 %0, %1;" : "=f"(y) : "f"(x)); return y;
}
__device__ __forceinline__ float rcpf(float x) {
    float y; asm("rcp.approx.ftz.f32 %0, %1;" : "=f"(y) : "f"(x)); return y;
}

__global__ void __launch_bounds__(Dn, 1) ltc_kernel(
    const float* __restrict__ X,       // (B,T,d)
    const float* __restrict__ in_w,    // (d)
    const float* __restrict__ in_b,    // (d)
    const float* __restrict__ out_w,   // (d)
    const float* __restrict__ out_b,   // (d)
    const float* __restrict__ gleak,   // (units)
    const float* __restrict__ vleak,   // (units)
    const float* __restrict__ cm,      // (units)
    const float* __restrict__ w,       // (units,units)
    const float* __restrict__ mu,      // (units,units)
    const float* __restrict__ sigma,   // (units,units)
    const float* __restrict__ erev,    // (units,units)
    const float* __restrict__ sw,      // (d,units)
    const float* __restrict__ smu,     // (d,units)
    const float* __restrict__ ssig,    // (d,units)
    const float* __restrict__ serev,   // (d,units)
    float* __restrict__ out)           // (B,d)
{
    const int j  = threadIdx.x;        // pair index, 0..d-1
    const int b  = blockIdx.x;         // batch index
    const int jc = j + Dn;             // partner unit

    // synapse flat indices (row-major (src, tgt))
    const int i_aa = j  * UNITS + j;   // j   -> j
    const int i_ca = jc * UNITS + j;   // j+d -> j
    const int i_cc = jc * UNITS + jc;  // j+d -> j+d
    const int i_ac = j  * UNITS + jc;  // j   -> j+d

    // sigmoid((v-mu)*sig) = 0.5 + 0.5*tanh(0.5*sig*v - 0.5*sig*mu)
    float sg, m;
    sg = __ldg(sigma + i_aa); m = __ldg(mu + i_aa);
    const float c1_aa = 0.5f * sg, c0_aa = -0.5f * sg * m;
    sg = __ldg(sigma + i_ca); m = __ldg(mu + i_ca);
    const float c1_ca = 0.5f * sg, c0_ca = -0.5f * sg * m;
    sg = __ldg(sigma + i_cc); m = __ldg(mu + i_cc);
    const float c1_cc = 0.5f * sg, c0_cc = -0.5f * sg * m;
    sg = __ldg(sigma + i_ac); m = __ldg(mu + i_ac);
    const float c1_ac = 0.5f * sg, c0_ac = -0.5f * sg * m;

    // w*sigmoid = 0.5*w + (0.5*w)*tanh ; same for w*erev
    const float w2_aa = 0.5f * __ldg(w + i_aa), we2_aa = w2_aa * __ldg(erev + i_aa);
    const float w2_ca = 0.5f * __ldg(w + i_ca), we2_ca = w2_ca * __ldg(erev + i_ca);
    const float w2_cc = 0.5f * __ldg(w + i_cc), we2_cc = w2_cc * __ldg(erev + i_cc);
    const float w2_ac = 0.5f * __ldg(w + i_ac), we2_ac = w2_ac * __ldg(erev + i_ac);

    // sensory synapses: src j -> tgt j (A) and src j -> tgt j+d (C)
    const int is_a = j * UNITS + j;
    const int is_c = j * UNITS + jc;
    sg = __ldg(ssig + is_a); m = __ldg(smu + is_a);
    const float sc1A = 0.5f * sg, sc0A = -0.5f * sg * m;
    sg = __ldg(ssig + is_c); m = __ldg(smu + is_c);
    const float sc1C = 0.5f * sg, sc0C = -0.5f * sg * m;
    const float sw2A = 0.5f * __ldg(sw + is_a), ser2A = sw2A * __ldg(serev + is_a);
    const float sw2C = 0.5f * __ldg(sw + is_c), ser2C = sw2C * __ldg(serev + is_c);

    // per-unit params
    const float glA = __ldg(gleak + j),  glC = __ldg(gleak + jc);
    const float vlA = __ldg(vleak + j),  vlC = __ldg(vleak + jc);
    const float cmtA = __ldg(cm + j)  * (float)UNFOLDS;
    const float cmtC = __ldg(cm + jc) * (float)UNFOLDS;

    // static parts of num/den bases (tanh half-weights folded in; EPS in den)
    const float numBaseA = fmaf(glA, vlA, we2_aa + we2_ca) + ser2A;
    const float numBaseC = fmaf(glC, vlC, we2_cc + we2_ac) + ser2C;
    const float denBaseA = cmtA + glA + w2_aa + w2_ca + EPSc + sw2A;
    const float denBaseC = cmtC + glC + w2_cc + w2_ac + EPSc + sw2C;

    const float inw = __ldg(in_w + j), inb = __ldg(in_b + j);
    const float ow  = __ldg(out_w + j), ob = __ldg(out_b + j);

    const float* xp = X + ((size_t)b * Tn) * Dn + j;

    // carry (num, D) with v = num * rcp(D); v0 = 0
    float numA = 0.0f, DA = 1.0f;
    float numC = 0.0f, DC = 1.0f;

    // ---- software-pipelined sensory state ----
    // current-timestep bases (nbA/dbA/nbC/dbC), computed one iteration ahead
    float xt0 = fmaf(__ldg(xp), inw, inb);
    float ths;
    ths = tanhf_(fmaf(sc1A, xt0, sc0A));
    float nbA = fmaf(ser2A, ths, numBaseA);
    float dbA = fmaf(sw2A,  ths, denBaseA);
    ths = tanhf_(fmaf(sc1C, xt0, sc0C));
    float nbC = fmaf(ser2C, ths, numBaseC);
    float dbC = fmaf(sw2C,  ths, denBaseC);

    float xnext = __ldg(xp + Dn);        // raw x for t=1

    #pragma unroll 2
    for (int t = 0; t < Tn; ++t) {
        // ---- compute NEXT timestep's sensory bases (independent of v) ----
        // consumed only at the bottom of this iteration, so ptxas can sink
        // these MUFUs/FFMAs into the unfold-chain stalls.
        const float xtn = fmaf(xnext, inw, inb);
        const float thsA_n = tanhf_(fmaf(sc1A, xtn, sc0A));
        const float thsC_n = tanhf_(fmaf(sc1C, xtn, sc0C));
        const float nbA_n = fmaf(ser2A, thsA_n, numBaseA);
        const float dbA_n = fmaf(sw2A,  thsA_n, denBaseA);
        const float nbC_n = fmaf(ser2C, thsC_n, numBaseC);
        const float dbC_n = fmaf(sw2C,  thsC_n, denBaseC);
        {   // branchless prefetch of x for t+2
            const int tnn = (t + 2 < Tn) ? (t + 2) : (Tn - 1);
            xnext = __ldg(xp + tnn * Dn);
        }

        #pragma unroll
        for (int u = 0; u < UNFOLDS; ++u) {
            const float rdA = rcpf(DA);
            const float rdC = rcpf(DC);
            // multipliers computed in the rcp shadow (depend only on num)
            const float pAA = c1_aa * numA;
            const float pAC = c1_ac * numA;
            const float pmA = cmtA * numA;
            const float pCA = c1_ca * numC;
            const float pCC = c1_cc * numC;
            const float pmC = cmtC * numC;

            const float thAA = tanhf_(fmaf(pAA, rdA, c0_aa));
            const float thAC = tanhf_(fmaf(pAC, rdA, c0_ac));
            const float thCA = tanhf_(fmaf(pCA, rdC, c0_ca));
            const float thCC = tanhf_(fmaf(pCC, rdC, c0_cc));

            // early partial sums (ready before tanh results)
            const float snA = fmaf(pmA, rdA, nbA);
            const float snC = fmaf(pmC, rdC, nbC);

            float nA = fmaf(we2_aa, thAA, snA);
            nA = fmaf(we2_ca, thCA, nA);
            float dA = fmaf(w2_aa, thAA, dbA);
            dA = fmaf(w2_ca, thCA, dA);

            float nC = fmaf(we2_cc, thCC, snC);
            nC = fmaf(we2_ac, thAC, nC);
            float dC = fmaf(w2_cc, thCC, dbC);
            dC = fmaf(w2_ac, thAC, dC);

            numA = nA; DA = dA;
            numC = nC; DC = dC;
        }

        // rotate pipelined sensory state
        nbA = nbA_n; dbA = dbA_n;
        nbC = nbC_n; dbC = dbC_n;
    }

    const float vA = numA * rcpf(DA);
    out[b * Dn + j] = fmaf(vA, ow, ob);
}

extern "C" void kernel_launch(void* const* d_in, const int* in_sizes, int n_in,
                              void* d_out, int out_size) {
    const float* X     = (const float*)d_in[0];
    const float* in_w  = (const float*)d_in[1];
    const float* in_b  = (const float*)d_in[2];
    const float* out_w = (const float*)d_in[3];
    const float* out_b = (const float*)d_in[4];
    const float* gleak = (const float*)d_in[5];
    const float* vleak = (const float*)d_in[6];
    const float* cmp   = (const float*)d_in[7];
    const float* w     = (const float*)d_in[8];
    const float* mu    = (const float*)d_in[9];
    const float* sigma = (const float*)d_in[10];
    const float* erev  = (const float*)d_in[11];
    const float* sw    = (const float*)d_in[12];
    const float* smu   = (const float*)d_in[13];
    const float* ssig  = (const float*)d_in[14];
    const float* serev = (const float*)d_in[15];
    float* out = (float*)d_out;

    const int B = in_sizes[0] / (Tn * Dn);   // 32
    ltc_kernel<<<B, Dn>>>(X, in_w, in_b, out_w, out_b,
                          gleak, vleak, cmp, w, mu, sigma, erev,
                          sw, smu, ssig, serev, out);
}